// round 15
// baseline (speedup 1.0000x reference)
#include <cuda_runtime.h>
#include <cuda_bf16.h>
#include <math.h>

#define N_NODES 8192
#define EMBED   64
#define HID0    256
#define HID1    256
#define HID2    128
#define ACTION  8192
#define IN_SIZE (N_NODES + EMBED)   // 8256
#define ROW_F4  (IN_SIZE / 4)       // 2064
#define RPB 8
#define NGROUPS 2
#define MV_BLOCKS (N_NODES / RPB / NGROUPS)   // 512
#define TREP 4
#define CLUST 8                      // tail cluster size

#if defined(__CUDA_ARCH__) && (__CUDA_ARCH__ >= 900)
#define PDL_TRIGGER()  cudaTriggerProgrammaticLaunchCompletion()
#define PDL_WAIT()     cudaGridDependencySynchronize()
#else
#define PDL_TRIGGER()
#define PDL_WAIT()
#endif

#define CLUSTER_SYNC() do { \
    asm volatile("barrier.cluster.arrive.aligned;" ::: "memory"); \
    asm volatile("barrier.cluster.wait.aligned;" ::: "memory"); \
} while (0)

// ---- scratch ----
__device__ float g_x[N_NODES];
__device__ float g_t_rep[TREP][HID0];
__device__ float g_fc1p[HID0];
__device__ float g_emb_g[EMBED];
__device__ float g_y1[HID0];
__device__ float g_y2[HID1];
__device__ float g_y3[HID2];

// dyn smem layout (floats) for k_tail_cluster
#define SM_GC2   0        // 16384 (CTA0 only)
#define SM_F1T   16384    // 2048  (32 rows x 64)
#define SM_F2W   18432    // 8192  (32 rows x 256)
#define SM_F3W   26624    // 4096  (16 rows x 256)
#define SM_F1B   30720    // 32
#define SM_F2B   30752    // 32
#define SM_F3B   30784    // 16
#define SM_GC2B  30800    // 64
#define SM_TOTALF 30864   // floats -> 123456 bytes

// K1: extract diagonal + zero t replicas
__global__ void k_diag(const float* __restrict__ state) {
    PDL_TRIGGER();
    int i = blockIdx.x * blockDim.x + threadIdx.x;
    if (i < TREP * HID0) ((float*)g_t_rep)[i] = 0.0f;
    if (i < N_NODES) g_x[i] = state[(size_t)i * (N_NODES + 1)];
}

// K2: blocks [0,512): matvec — 2 sequential row-groups of 8 rows (single wave)
//     blocks [512,768): fc1 partials (independent -> overlap diag)
__global__ void __launch_bounds__(256) k_matvec_fc1p(const float* __restrict__ state,
                                                     const int* __restrict__ start_p,
                                                     const float* __restrict__ gc1_w,
                                                     const float* __restrict__ gc1_b,
                                                     const float* __restrict__ fc1_w) {
    PDL_TRIGGER();
    int tid = threadIdx.x;
    if (blockIdx.x < MV_BLOCKS) {
        float wj = gc1_w[tid];
        float bj = gc1_b[tid];
        int st = *start_p;

        PDL_WAIT();

        int lane = tid & 31, wid = tid >> 5;
        __shared__ float sh[RPB][8];
        __shared__ float s_sh[RPB];
        __shared__ float a_sh[RPB];
        const float4* __restrict__ xp = (const float4*)g_x;
        float ct = 0.0f;

        #pragma unroll
        for (int g = 0; g < NGROUPS; g++) {
            int r0 = (blockIdx.x + g * MV_BLOCKS) * RPB;
            const float4* __restrict__ base =
                (const float4*)(state + (size_t)r0 * N_NODES);
            float acc[RPB];
            #pragma unroll
            for (int r = 0; r < RPB; r++) acc[r] = 0.0f;
            for (int j = tid; j < N_NODES / 4; j += 256) {
                float4 xv = xp[j];
                #pragma unroll
                for (int r = 0; r < RPB; r++) {
                    float4 a = __ldcs(&base[(size_t)r * (N_NODES / 4) + j]);
                    acc[r] += a.x * xv.x + a.y * xv.y + a.z * xv.z + a.w * xv.w;
                }
            }
            #pragma unroll
            for (int r = 0; r < RPB; r++)
                #pragma unroll
                for (int o = 16; o; o >>= 1)
                    acc[r] += __shfl_down_sync(0xffffffffu, acc[r], o);
            __syncthreads();
            if (lane == 0) {
                #pragma unroll
                for (int r = 0; r < RPB; r++) sh[r][wid] = acc[r];
            }
            __syncthreads();
            if (tid < RPB * 8) {
                int r = tid >> 3, w = tid & 7;
                float v = sh[r][w];
                v += __shfl_down_sync(0xffffffffu, v, 4, 8);
                v += __shfl_down_sync(0xffffffffu, v, 2, 8);
                v += __shfl_down_sync(0xffffffffu, v, 1, 8);
                if (w == 0) {
                    int row = r0 + r;
                    float xi = g_x[row];
                    s_sh[r] = v - xi * xi;
                    a_sh[r] = (row == st) ? 0.0f : state[(size_t)st * N_NODES + row];
                }
            }
            __syncthreads();
            #pragma unroll
            for (int r = 0; r < RPB; r++)
                ct += a_sh[r] * fmaxf(fmaf(s_sh[r], wj, bj), 0.0f);
        }
        atomicAdd(&g_t_rep[blockIdx.x & (TREP - 1)][tid], ct);
    } else {
        int r = blockIdx.x - MV_BLOCKS;
        int st = *start_p;
        const float4* __restrict__ w4 = (const float4*)(fc1_w + (size_t)r * IN_SIZE);
        const float4* __restrict__ s4 = (const float4*)(state + (size_t)st * N_NODES);
        float acc = 0.0f;
        #pragma unroll 8
        for (int j = tid; j < N_NODES / 4; j += 256) {
            float4 a = __ldcs(&w4[j]);
            float4 b = s4[j];
            acc += a.x * b.x + a.y * b.y + a.z * b.z + a.w * b.w;
        }
        int lane = tid & 31, wid = tid >> 5;
        #pragma unroll
        for (int o = 16; o; o >>= 1) acc += __shfl_down_sync(0xffffffffu, acc, o);
        __shared__ float sh2[8];
        if (lane == 0) sh2[wid] = acc;
        __syncthreads();
        if (tid < 8) {
            float v = sh2[tid];
            v += __shfl_down_sync(0xffu, v, 4, 8);
            v += __shfl_down_sync(0xffu, v, 2, 8);
            v += __shfl_down_sync(0xffu, v, 1, 8);
            if (tid == 0) g_fc1p[r] = v;
        }
    }
}

// K3: cluster of 8 CTAs x 256 threads. emb -> fc1 -> fc2 -> fc3 with cluster
// barriers instead of PDL boundaries. Each CTA stages its weight slice pre-gate.
__global__ void __launch_bounds__(256) k_tail_cluster(const float* __restrict__ gc2_w,
                                                      const float* __restrict__ gc2_b,
                                                      const float* __restrict__ fc1_w,
                                                      const float* __restrict__ fc1_b,
                                                      const float* __restrict__ fc2_w,
                                                      const float* __restrict__ fc2_b,
                                                      const float* __restrict__ fc3_w,
                                                      const float* __restrict__ fc3_b) {
    PDL_TRIGGER();
    extern __shared__ float dyn[];
    int tid = threadIdx.x;
    int rank = blockIdx.x;   // grid == one cluster of 8

    // ---- pre-gate weight staging (overlaps matvec) ----
    {
        // fc1 tail slice: rows [rank*32, rank*32+32), 16 f4 per row
        float4* d = (float4*)(dyn + SM_F1T);
        const float4* w4 = (const float4*)fc1_w;
        for (int i = tid; i < 512; i += 256) {
            int rl = i >> 4, c = i & 15;
            d[i] = w4[(size_t)(rank * 32 + rl) * ROW_F4 + (N_NODES / 4) + c];
        }
        // fc2 slice: rows [rank*32, +32) x 256 cols = 2048 f4, contiguous
        float4* d2 = (float4*)(dyn + SM_F2W);
        const float4* s2 = (const float4*)(fc2_w + (size_t)rank * 32 * HID0);
        for (int i = tid; i < 2048; i += 256) d2[i] = s2[i];
        // fc3 slice: rows [rank*16, +16) x 256 = 1024 f4
        float4* d3 = (float4*)(dyn + SM_F3W);
        const float4* s3 = (const float4*)(fc3_w + (size_t)rank * 16 * HID1);
        for (int i = tid; i < 1024; i += 256) d3[i] = s3[i];
        if (tid < 32) dyn[SM_F1B + tid] = fc1_b[rank * 32 + tid];
        if (tid < 32) dyn[SM_F2B + tid] = fc2_b[rank * 32 + tid];
        if (tid < 16) dyn[SM_F3B + tid] = fc3_b[rank * 16 + tid];
        if (rank == 0) {
            float4* dg = (float4*)(dyn + SM_GC2);
            const float4* sg = (const float4*)gc2_w;
            for (int i = tid; i < 4096; i += 256) dg[i] = sg[i];
            if (tid < EMBED) dyn[SM_GC2B + tid] = gc2_b[tid];
        }
    }
    __syncthreads();

    PDL_WAIT();   // matvec grid complete: g_t_rep, g_fc1p ready

    // ---- stage A: CTA0 computes emb = log_softmax(relu(t @ gc2 + b)) ----
    if (rank == 0) {
        __shared__ float ts[HID0];
        __shared__ float part[4][EMBED];
        __shared__ float hv[EMBED];
        __shared__ float red[1];
        ts[tid] = g_t_rep[0][tid] + g_t_rep[1][tid] + g_t_rep[2][tid] + g_t_rep[3][tid];
        __syncthreads();
        {
            int c = tid & 63, p = tid >> 6;
            float u = 0.0f;
            #pragma unroll 8
            for (int j = p * 64; j < p * 64 + 64; j++)
                u = fmaf(ts[j], dyn[SM_GC2 + j * EMBED + c], u);
            part[p][c] = u;
        }
        __syncthreads();
        if (tid < EMBED) {
            float h = part[0][tid] + part[1][tid] + part[2][tid] + part[3][tid]
                      + dyn[SM_GC2B + tid];
            hv[tid] = fmaxf(h, 0.0f);
        }
        __syncthreads();
        if (tid < 32) {
            float m = fmaxf(hv[tid], hv[tid + 32]);
            #pragma unroll
            for (int o = 16; o; o >>= 1) m = fmaxf(m, __shfl_xor_sync(0xffffffffu, m, o));
            float s = expf(hv[tid] - m) + expf(hv[tid + 32] - m);
            #pragma unroll
            for (int o = 16; o; o >>= 1) s += __shfl_xor_sync(0xffffffffu, s, o);
            if (tid == 0) red[0] = m + logf(s);
        }
        __syncthreads();
        if (tid < EMBED) g_emb_g[tid] = hv[tid] - red[0];
        __threadfence();
    }
    CLUSTER_SYNC();

    // ---- stage B: fc1 finish — 32 rows per CTA, 8 threads/row (f4 strided) ----
    __shared__ __align__(16) float emb_s[EMBED];
    __shared__ __align__(16) float y1s[HID0];
    __shared__ __align__(16) float y2s[HID1];
    if (tid < EMBED) emb_s[tid] = __ldcg(&g_emb_g[tid]);
    __syncthreads();
    {
        int rl = tid >> 3, q = tid & 7;
        const float4* wrow = (const float4*)(dyn + SM_F1T + rl * EMBED);
        const float4* e4 = (const float4*)emb_s;
        float acc = 0.0f;
        #pragma unroll
        for (int i = 0; i < 2; i++) {
            float4 w = wrow[q + 8 * i];
            float4 e = e4[q + 8 * i];
            acc += w.x * e.x + w.y * e.y + w.z * e.z + w.w * e.w;
        }
        acc += __shfl_down_sync(0xffffffffu, acc, 4, 8);
        acc += __shfl_down_sync(0xffffffffu, acc, 2, 8);
        acc += __shfl_down_sync(0xffffffffu, acc, 1, 8);
        if (q == 0) {
            int r = rank * 32 + rl;
            g_y1[r] = fmaxf(acc + g_fc1p[r] + dyn[SM_F1B + rl], 0.0f);
        }
    }
    __threadfence();
    CLUSTER_SYNC();

    // ---- stage C: fc2 — 32 outputs per CTA, 8 threads/output ----
    y1s[tid] = __ldcg(&g_y1[tid]);
    __syncthreads();
    {
        int ol = tid >> 3, q = tid & 7;
        const float4* wrow = (const float4*)(dyn + SM_F2W + ol * HID0);
        const float4* y4 = (const float4*)y1s;
        float acc = 0.0f;
        #pragma unroll
        for (int i = 0; i < 8; i++) {
            float4 w = wrow[q + 8 * i];
            float4 y = y4[q + 8 * i];
            acc += w.x * y.x + w.y * y.y + w.z * y.z + w.w * y.w;
        }
        acc += __shfl_down_sync(0xffffffffu, acc, 4, 8);
        acc += __shfl_down_sync(0xffffffffu, acc, 2, 8);
        acc += __shfl_down_sync(0xffffffffu, acc, 1, 8);
        if (q == 0) g_y2[rank * 32 + ol] = fmaxf(acc + dyn[SM_F2B + ol], 0.0f);
    }
    __threadfence();
    CLUSTER_SYNC();

    // ---- stage D: fc3 — 16 outputs per CTA, 16 threads/output ----
    y2s[tid] = __ldcg(&g_y2[tid]);
    __syncthreads();
    {
        int ol = tid >> 4, q = tid & 15;
        const float4* wrow = (const float4*)(dyn + SM_F3W + ol * HID1);
        const float4* y4 = (const float4*)y2s;
        float acc = 0.0f;
        #pragma unroll
        for (int i = 0; i < 4; i++) {
            float4 w = wrow[q + 16 * i];
            float4 y = y4[q + 16 * i];
            acc += w.x * y.x + w.y * y.y + w.z * y.z + w.w * y.w;
        }
        acc += __shfl_down_sync(0xffffffffu, acc, 8, 16);
        acc += __shfl_down_sync(0xffffffffu, acc, 4, 16);
        acc += __shfl_down_sync(0xffffffffu, acc, 2, 16);
        acc += __shfl_down_sync(0xffffffffu, acc, 1, 16);
        if (q == 0) g_y3[rank * 16 + ol] = fmaxf(acc + dyn[SM_F3B + ol], 0.0f);
    }
}

// K4: fc4 — warp per output; weights preloaded pre-gate.
__global__ void __launch_bounds__(256) k_fc4(const float* __restrict__ fc4_w,
                                             const float* __restrict__ fc4_b,
                                             float* __restrict__ out) {
    int tid = threadIdx.x, warp = tid >> 5, lane = tid & 31;
    int a = blockIdx.x * 8 + warp;
    float4 w = ((const float4*)(fc4_w + (size_t)a * HID2))[lane];
    float b = fc4_b[a];
    PDL_WAIT();   // need g_y3
    float4 y = ((const float4*)g_y3)[lane];
    float acc = w.x * y.x + w.y * y.y + w.z * y.z + w.w * y.w;
    #pragma unroll
    for (int o = 16; o; o >>= 1) acc += __shfl_down_sync(0xffffffffu, acc, o);
    if (lane == 0) out[a] = fmaxf(acc + b, 0.0f);
}

// ---- host launch helpers ----
template <typename... Args>
static inline void launch_pdl(void (*kern)(Args...), dim3 grid, dim3 block,
                              unsigned smem, Args... args) {
    cudaLaunchConfig_t cfg = {};
    cfg.gridDim = grid;
    cfg.blockDim = block;
    cfg.dynamicSmemBytes = smem;
    cfg.stream = 0;
    cudaLaunchAttribute attr[1];
    attr[0].id = cudaLaunchAttributeProgrammaticStreamSerialization;
    attr[0].val.programmaticStreamSerializationAllowed = 1;
    cfg.attrs = attr;
    cfg.numAttrs = 1;
    cudaLaunchKernelEx(&cfg, kern, args...);
}

template <typename... Args>
static inline void launch_pdl_cluster(void (*kern)(Args...), dim3 grid, dim3 block,
                                      unsigned smem, unsigned csize, Args... args) {
    cudaLaunchConfig_t cfg = {};
    cfg.gridDim = grid;
    cfg.blockDim = block;
    cfg.dynamicSmemBytes = smem;
    cfg.stream = 0;
    cudaLaunchAttribute attr[2];
    attr[0].id = cudaLaunchAttributeProgrammaticStreamSerialization;
    attr[0].val.programmaticStreamSerializationAllowed = 1;
    attr[1].id = cudaLaunchAttributeClusterDimension;
    attr[1].val.clusterDim.x = csize;
    attr[1].val.clusterDim.y = 1;
    attr[1].val.clusterDim.z = 1;
    cfg.attrs = attr;
    cfg.numAttrs = 2;
    cudaLaunchKernelEx(&cfg, kern, args...);
}

extern "C" void kernel_launch(void* const* d_in, const int* in_sizes, int n_in,
                              void* d_out, int out_size) {
    const float* state = (const float*)d_in[0];
    const int*   start = (const int*)d_in[1];
    const float* gc1_w = (const float*)d_in[2];
    const float* gc1_b = (const float*)d_in[3];
    const float* gc2_w = (const float*)d_in[4];
    const float* gc2_b = (const float*)d_in[5];
    const float* fc1_w = (const float*)d_in[6];
    const float* fc1_b = (const float*)d_in[7];
    const float* fc2_w = (const float*)d_in[8];
    const float* fc2_b = (const float*)d_in[9];
    const float* fc3_w = (const float*)d_in[10];
    const float* fc3_b = (const float*)d_in[11];
    const float* fc4_w = (const float*)d_in[12];
    const float* fc4_b = (const float*)d_in[13];
    float* out = (float*)d_out;

    const unsigned TAIL_SMEM = SM_TOTALF * sizeof(float);   // ~120.6 KB
    static bool attr_set = false;
    if (!attr_set) {
        cudaFuncSetAttribute(k_tail_cluster,
                             cudaFuncAttributeMaxDynamicSharedMemorySize, TAIL_SMEM);
        attr_set = true;
    }

    k_diag<<<N_NODES / 256, 256>>>(state);
    launch_pdl(k_matvec_fc1p, dim3(MV_BLOCKS + HID0), dim3(256), 0u,
               state, start, gc1_w, gc1_b, fc1_w);
    launch_pdl_cluster(k_tail_cluster, dim3(CLUST), dim3(256), TAIL_SMEM, CLUST,
                       gc2_w, gc2_b, fc1_w, fc1_b, fc2_w, fc2_b, fc3_w, fc3_b);
    launch_pdl(k_fc4, dim3(ACTION / 8), dim3(256), 0u, fc4_w, fc4_b, out);
}